// round 1
// baseline (speedup 1.0000x reference)
#include <cuda_runtime.h>
#include <math.h>

// ---------------- problem constants ----------------
#define B_    32
#define T_    12
#define FIN   16
#define FOUT  32
#define NN    2048
#define BT    (B_*T_)        // 384
#define R1    (BT*FIN)       // 6144
#define R2    (BT*FOUT)      // 12288
#define NCHUNK 8             // NN / 256

// ---------------- scratch (device globals; no allocs) ----------------
__device__ float g_att0[BT];
__device__ float g_att[BT];
__device__ float g_xatt[(size_t)R1 * NN];          //  50 MB
__device__ float g_P1[(size_t)2 * R1 * NN];        // 100 MB (k=1,2)
__device__ float g_xg1[(size_t)R2 * NN];           // 100 MB
__device__ float g_P2[(size_t)2 * R2 * NN];        // 200 MB
__device__ float g_xg2[(size_t)R2 * NN];           // 100 MB
__device__ float g_xt1[(size_t)R2 * NN];           // 100 MB
__device__ float g_y[(size_t)R2 * NN];             // 100 MB
__device__ float g_part[(size_t)BT * FOUT * NCHUNK * 2]; // partial sum/sumsq

// ---------------- SE attention: mean over (f,n) ----------------
__global__ void k_mean(const float* __restrict__ x) {
    int bt = blockIdx.x;
    const float* p = x + (size_t)bt * FIN * NN;
    float s = 0.f;
    for (int i = threadIdx.x; i < FIN * NN; i += 256) s += p[i];
    __shared__ float sm[8];
    for (int o = 16; o; o >>= 1) s += __shfl_xor_sync(~0u, s, o);
    if ((threadIdx.x & 31) == 0) sm[threadIdx.x >> 5] = s;
    __syncthreads();
    if (threadIdx.x < 8) {
        s = sm[threadIdx.x];
        for (int o = 4; o; o >>= 1) s += __shfl_xor_sync(0xffu, s, o);
        if (threadIdx.x == 0) g_att0[bt] = s / (float)(FIN * NN);
    }
}

// ---------------- SE MLP: [12]->relu[3]->sigmoid[12] ----------------
__global__ void k_mlp(const float* __restrict__ w1, const float* __restrict__ b1,
                      const float* __restrict__ w2, const float* __restrict__ b2) {
    int b = threadIdx.x;
    if (b >= B_) return;
    float h[3];
    #pragma unroll
    for (int j = 0; j < 3; j++) {
        float s = b1[j];
        #pragma unroll
        for (int t = 0; t < T_; t++) s += w1[j * T_ + t] * g_att0[b * T_ + t];
        h[j] = fmaxf(s, 0.f);
    }
    #pragma unroll
    for (int t = 0; t < T_; t++) {
        float s = b2[t];
        #pragma unroll
        for (int j = 0; j < 3; j++) s += w2[t * 3 + j] * h[j];
        g_att[b * T_ + t] = 1.f / (1.f + expf(-s));
    }
}

// ---------------- x_att = x * att[b,t] ----------------
__global__ void k_xatt(const float* __restrict__ x) {
    size_t i = (size_t)blockIdx.x * 256 + threadIdx.x;
    int bt = (int)(i / ((size_t)FIN * NN));
    g_xatt[i] = x[i] * g_att[bt];
}

// ---------------- SGEMM: C[k2] = A @ cheb[k2+1], 128x128x8, 8x8/thread ----
template<int LAYER>
__global__ __launch_bounds__(256)
void k_sgemm(const float* __restrict__ cheb) {
    constexpr int R = (LAYER == 1) ? R1 : R2;
    const float* A = (LAYER == 1) ? g_xatt : g_xg1;
    float* C = (LAYER == 1) ? g_P1 : g_P2;

    __shared__ float As[8][128];
    __shared__ float Bs[8][128];

    const float* Bp = cheb + ((size_t)(blockIdx.z + 1)) * NN * NN;
    float* Cp = C + (size_t)blockIdx.z * R * NN;
    int row0 = blockIdx.y * 128, col0 = blockIdx.x * 128;
    int tid = threadIdx.x;
    int aRow = tid >> 1, aK = (tid & 1) * 4;
    int bRow = tid >> 5, bCol = (tid & 31) * 4;
    int tx = tid & 15, ty = tid >> 4;

    const float* Aload = A + (size_t)(row0 + aRow) * NN + aK;
    const float* Bload = Bp + (size_t)bRow * NN + col0 + bCol;

    float acc[8][8] = {};
    for (int m0 = 0; m0 < NN; m0 += 8) {
        float4 a4 = *(const float4*)(Aload + m0);
        float4 b4 = *(const float4*)(Bload + (size_t)m0 * NN);
        As[aK + 0][aRow] = a4.x; As[aK + 1][aRow] = a4.y;
        As[aK + 2][aRow] = a4.z; As[aK + 3][aRow] = a4.w;
        *(float4*)&Bs[bRow][bCol] = b4;
        __syncthreads();
        #pragma unroll
        for (int kk = 0; kk < 8; kk++) {
            float ra[8], rb[8];
            *(float4*)(ra)     = *(const float4*)&As[kk][ty * 4];
            *(float4*)(ra + 4) = *(const float4*)&As[kk][64 + ty * 4];
            *(float4*)(rb)     = *(const float4*)&Bs[kk][tx * 4];
            *(float4*)(rb + 4) = *(const float4*)&Bs[kk][64 + tx * 4];
            #pragma unroll
            for (int i = 0; i < 8; i++)
                #pragma unroll
                for (int j = 0; j < 8; j++)
                    acc[i][j] += ra[i] * rb[j];
        }
        __syncthreads();
    }
    #pragma unroll
    for (int i = 0; i < 8; i++) {
        int r = row0 + ((i < 4) ? (ty * 4 + i) : (64 + ty * 4 + i - 4));
        float* cr = Cp + (size_t)r * NN + col0;
        *(float4*)(cr + tx * 4)      = make_float4(acc[i][0], acc[i][1], acc[i][2], acc[i][3]);
        *(float4*)(cr + 64 + tx * 4) = make_float4(acc[i][4], acc[i][5], acc[i][6], acc[i][7]);
    }
}

// ---------------- combine layer1: theta-mix over (k,f), relu ----------------
__global__ __launch_bounds__(256)
void k_combine1(const float* __restrict__ theta1) {
    __shared__ float th[3 * FIN * FOUT];
    for (int i = threadIdx.x; i < 3 * FIN * FOUT; i += 256) th[i] = theta1[i];
    __syncthreads();
    int bt = blockIdx.y;
    int n = blockIdx.x * 256 + threadIdx.x;
    float acc[FOUT] = {};
    // k=0: cheb[0] == I -> use x_att directly
    const float* x0 = g_xatt + ((size_t)bt * FIN) * NN + n;
    #pragma unroll
    for (int f = 0; f < FIN; f++) {
        float v = x0[(size_t)f * NN];
        const float* tp = th + f * FOUT;
        #pragma unroll
        for (int o = 0; o < FOUT; o++) acc[o] += tp[o] * v;
    }
    #pragma unroll
    for (int k2 = 0; k2 < 2; k2++) {
        const float* p = g_P1 + ((size_t)k2 * R1 + bt * FIN) * NN + n;
        const float* tk = th + (k2 + 1) * FIN * FOUT;
        #pragma unroll
        for (int f = 0; f < FIN; f++) {
            float v = p[(size_t)f * NN];
            #pragma unroll
            for (int o = 0; o < FOUT; o++) acc[o] += tk[f * FOUT + o] * v;
        }
    }
    float* out = g_xg1 + ((size_t)bt * FOUT) * NN + n;
    #pragma unroll
    for (int o = 0; o < FOUT; o++) out[(size_t)o * NN] = fmaxf(acc[o], 0.f);
}

// ---------------- combine layer2 ----------------
__global__ __launch_bounds__(256)
void k_combine2(const float* __restrict__ theta2) {
    __shared__ float th[3 * FOUT * FOUT];
    for (int i = threadIdx.x; i < 3 * FOUT * FOUT; i += 256) th[i] = theta2[i];
    __syncthreads();
    int bt = blockIdx.y;
    int n = blockIdx.x * 256 + threadIdx.x;
    float acc[FOUT] = {};
    const float* x0 = g_xg1 + ((size_t)bt * FOUT) * NN + n;
    #pragma unroll
    for (int f = 0; f < FOUT; f++) {
        float v = x0[(size_t)f * NN];
        const float* tp = th + f * FOUT;
        #pragma unroll
        for (int o = 0; o < FOUT; o++) acc[o] += tp[o] * v;
    }
    #pragma unroll
    for (int k2 = 0; k2 < 2; k2++) {
        const float* p = g_P2 + ((size_t)k2 * R2 + bt * FOUT) * NN + n;
        const float* tk = th + (k2 + 1) * FOUT * FOUT;
        #pragma unroll
        for (int f = 0; f < FOUT; f++) {
            float v = p[(size_t)f * NN];
            #pragma unroll
            for (int o = 0; o < FOUT; o++) acc[o] += tk[f * FOUT + o] * v;
        }
    }
    float* out = g_xg2 + ((size_t)bt * FOUT) * NN + n;
    #pragma unroll
    for (int o = 0; o < FOUT; o++) out[(size_t)o * NN] = fmaxf(acc[o], 0.f);
}

// ---------------- temporal conv 1 (kernel (1,2), circular self-pad, relu) ---
__global__ __launch_bounds__(256)
void k_tconv1(const float* __restrict__ w, const float* __restrict__ bias) {
    __shared__ float ws[FOUT * FOUT * 2];
    for (int i = threadIdx.x; i < FOUT * FOUT * 2; i += 256) ws[i] = w[i];
    __syncthreads();
    int bt = blockIdx.y;
    int b = bt / T_, t = bt % T_;
    int ta = (t == 0) ? 10 : (t - 1);
    int tb = (t == 0) ? 11 : t;
    int n = blockIdx.x * 256 + threadIdx.x;
    const float* pa = g_xg2 + ((size_t)(b * T_ + ta) * FOUT) * NN + n;
    const float* pb = g_xg2 + ((size_t)(b * T_ + tb) * FOUT) * NN + n;
    float acc[FOUT];
    #pragma unroll
    for (int o = 0; o < FOUT; o++) acc[o] = bias[o];
    #pragma unroll
    for (int gg = 0; gg < FOUT; gg++) {
        float v0 = pa[(size_t)gg * NN], v1 = pb[(size_t)gg * NN];
        #pragma unroll
        for (int o = 0; o < FOUT; o++)
            acc[o] += ws[(o * FOUT + gg) * 2] * v0 + ws[(o * FOUT + gg) * 2 + 1] * v1;
    }
    float* out = g_xt1 + ((size_t)bt * FOUT) * NN + n;
    #pragma unroll
    for (int o = 0; o < FOUT; o++) out[(size_t)o * NN] = fmaxf(acc[o], 0.f);
}

// ---------------- temporal conv 2 + residual 1x1 + partial LN stats --------
__global__ __launch_bounds__(256)
void k_tconv2(const float* __restrict__ x,
              const float* __restrict__ w2, const float* __restrict__ b2,
              const float* __restrict__ rw, const float* __restrict__ rb) {
    __shared__ float ws[FOUT * FOUT * 2];
    __shared__ float rs[FOUT * FIN];
    __shared__ float red[2][8][FOUT];  // [sum/sumsq][warp][o]
    for (int i = threadIdx.x; i < FOUT * FOUT * 2; i += 256) ws[i] = w2[i];
    for (int i = threadIdx.x; i < FOUT * FIN; i += 256) rs[i] = rw[i];
    __syncthreads();
    int bt = blockIdx.y;
    int b = bt / T_, t = bt % T_;
    int ta = (t == 0) ? 10 : (t - 1);
    int tb = (t == 0) ? 11 : t;
    int n = blockIdx.x * 256 + threadIdx.x;
    const float* pa = g_xt1 + ((size_t)(b * T_ + ta) * FOUT) * NN + n;
    const float* pb = g_xt1 + ((size_t)(b * T_ + tb) * FOUT) * NN + n;
    float acc[FOUT];
    #pragma unroll
    for (int o = 0; o < FOUT; o++) acc[o] = b2[o];
    #pragma unroll
    for (int gg = 0; gg < FOUT; gg++) {
        float v0 = pa[(size_t)gg * NN], v1 = pb[(size_t)gg * NN];
        #pragma unroll
        for (int o = 0; o < FOUT; o++)
            acc[o] += ws[(o * FOUT + gg) * 2] * v0 + ws[(o * FOUT + gg) * 2 + 1] * v1;
    }
    // relu on the temporal-conv part, then add residual (no relu)
    #pragma unroll
    for (int o = 0; o < FOUT; o++) acc[o] = fmaxf(acc[o], 0.f) + rb[o];
    const float* xr = x + ((size_t)bt * FIN) * NN + n;
    #pragma unroll
    for (int f = 0; f < FIN; f++) {
        float v = xr[(size_t)f * NN];
        #pragma unroll
        for (int o = 0; o < FOUT; o++) acc[o] += rs[o * FIN + f] * v;
    }
    float* out = g_y + ((size_t)bt * FOUT) * NN + n;
    int warp = threadIdx.x >> 5, lane = threadIdx.x & 31;
    #pragma unroll
    for (int o = 0; o < FOUT; o++) {
        float v = acc[o];
        out[(size_t)o * NN] = v;
        float s = v, s2 = v * v;
        #pragma unroll
        for (int d = 16; d; d >>= 1) {
            s  += __shfl_xor_sync(~0u, s, d);
            s2 += __shfl_xor_sync(~0u, s2, d);
        }
        if (lane == 0) { red[0][warp][o] = s; red[1][warp][o] = s2; }
    }
    __syncthreads();
    // warp 0: final per-o partial over the 8 warps (deterministic)
    if (threadIdx.x < FOUT) {
        int o = threadIdx.x;
        float s = 0.f, s2 = 0.f;
        #pragma unroll
        for (int wdx = 0; wdx < 8; wdx++) { s += red[0][wdx][o]; s2 += red[1][wdx][o]; }
        size_t base = (((size_t)bt * FOUT + o) * NCHUNK + blockIdx.x) * 2;
        g_part[base] = s;
        g_part[base + 1] = s2;
    }
}

// ---------------- layernorm over n + affine + relu -> out ----------------
__global__ __launch_bounds__(256)
void k_ln(const float* __restrict__ lng, const float* __restrict__ lnb,
          float* __restrict__ out) {
    int bto = blockIdx.x;                       // (b,t,o)
    int n = blockIdx.y * 256 + threadIdx.x;
    float s = 0.f, s2 = 0.f;
    #pragma unroll
    for (int c = 0; c < NCHUNK; c++) {
        size_t base = (((size_t)bto) * NCHUNK + c) * 2;
        s += g_part[base];
        s2 += g_part[base + 1];
    }
    float mu = s / (float)NN;
    float var = s2 / (float)NN - mu * mu;
    float rstd = rsqrtf(var + 1e-5f);
    float v = g_y[(size_t)bto * NN + n];
    v = (v - mu) * rstd * lng[n] + lnb[n];
    out[(size_t)bto * NN + n] = fmaxf(v, 0.f);
}

// ---------------- launch ----------------
extern "C" void kernel_launch(void* const* d_in, const int* in_sizes, int n_in,
                              void* d_out, int out_size) {
    const float* x      = (const float*)d_in[0];
    const float* cheb   = (const float*)d_in[1];
    const float* theta1 = (const float*)d_in[2];
    const float* theta2 = (const float*)d_in[3];
    const float* m1w    = (const float*)d_in[4];
    const float* m1b    = (const float*)d_in[5];
    const float* m2w    = (const float*)d_in[6];
    const float* m2b    = (const float*)d_in[7];
    const float* tc1w   = (const float*)d_in[8];
    const float* tc1b   = (const float*)d_in[9];
    const float* tc2w   = (const float*)d_in[10];
    const float* tc2b   = (const float*)d_in[11];
    const float* resw   = (const float*)d_in[12];
    const float* resb   = (const float*)d_in[13];
    const float* lng    = (const float*)d_in[14];
    const float* lnb    = (const float*)d_in[15];
    float* out = (float*)d_out;

    // SE attention
    k_mean<<<BT, 256>>>(x);
    k_mlp<<<1, 32>>>(m1w, m1b, m2w, m2b);
    k_xatt<<<(int)(((size_t)R1 * NN) / 256), 256>>>(x);

    // gconv layer 1: graph-mix (k=1,2) then theta-mix (+identity k=0)
    dim3 g1(NN / 128, R1 / 128, 2);
    k_sgemm<1><<<g1, 256>>>(cheb);
    k_combine1<<<dim3(NCHUNK, BT), 256>>>(theta1);

    // gconv layer 2
    dim3 g2(NN / 128, R2 / 128, 2);
    k_sgemm<2><<<g2, 256>>>(cheb);
    k_combine2<<<dim3(NCHUNK, BT), 256>>>(theta2);

    // temporal convs + residual + layernorm
    k_tconv1<<<dim3(NCHUNK, BT), 256>>>(tc1w, tc1b);
    k_tconv2<<<dim3(NCHUNK, BT), 256>>>(x, tc2w, tc2b, resw, resb);
    k_ln<<<dim3(BT * FOUT, NCHUNK), 256>>>(lng, lnb, out);
}

// round 4
// speedup vs baseline: 2.3608x; 2.3608x over previous
#include <cuda_runtime.h>
#include <cuda_bf16.h>
#include <math.h>
#include <stdint.h>

// ---------------- problem constants ----------------
#define B_    32
#define T_    12
#define FIN   16
#define FOUT  32
#define NN    2048
#define BT    (B_*T_)        // 384
#define R1    (BT*FIN)       // 6144
#define R2    (BT*FOUT)      // 12288
#define NCHUNK 8             // NN / 256
#define NSQ   ((size_t)NN*NN)

// GEMM tiling
#define BM 128
#define BN 128
#define BK 64                // bf16 k-elements per stage (=128B rows)
#define NIT (NN/BK)          // 32
#define STAGE_BYTES (4*16384)   // Ah,Al,Bh,Bl tiles: 128x64 bf16 each
#define DYN_SMEM (2*STAGE_BYTES)

// ---------------- scratch (device globals; no allocs) ----------------
__device__ float g_att0[BT];
__device__ float g_att[BT];
__device__ __nv_bfloat16 g_xatth[(size_t)R1 * NN];
__device__ __nv_bfloat16 g_xattl[(size_t)R1 * NN];
__device__ __nv_bfloat16 g_chebh[(size_t)2 * NSQ];
__device__ __nv_bfloat16 g_chebl[(size_t)2 * NSQ];
__device__ float g_P1[(size_t)2 * R1 * NN];
__device__ __nv_bfloat16 g_xg1h[(size_t)R2 * NN];
__device__ __nv_bfloat16 g_xg1l[(size_t)R2 * NN];
__device__ float g_P2[(size_t)2 * R2 * NN];
__device__ float g_xg2[(size_t)R2 * NN];
__device__ float g_xt1[(size_t)R2 * NN];
__device__ float g_y[(size_t)R2 * NN];
__device__ float g_part[(size_t)BT * FOUT * NCHUNK * 2];

// ---------------- PTX helpers (baseline sm_80+ features only) ----------------
__device__ __forceinline__ uint32_t smem_u32(const void* p) {
    return (uint32_t)__cvta_generic_to_shared(p);
}
__device__ __forceinline__ void cp16(uint32_t dst, const void* src) {
    asm volatile("cp.async.cg.shared.global [%0], [%1], 16;\n" :: "r"(dst), "l"(src));
}
__device__ __forceinline__ void ldm4(uint32_t* r, uint32_t addr) {
    asm volatile("ldmatrix.sync.aligned.m8n8.x4.shared.b16 {%0,%1,%2,%3}, [%4];"
                 : "=r"(r[0]), "=r"(r[1]), "=r"(r[2]), "=r"(r[3]) : "r"(addr));
}
__device__ __forceinline__ void mma16816(float* d, const uint32_t* a, const uint32_t* b) {
    asm volatile(
        "mma.sync.aligned.m16n8k16.row.col.f32.bf16.bf16.f32 "
        "{%0,%1,%2,%3}, {%4,%5,%6,%7}, {%8,%9}, {%0,%1,%2,%3};"
        : "+f"(d[0]), "+f"(d[1]), "+f"(d[2]), "+f"(d[3])
        : "r"(a[0]), "r"(a[1]), "r"(a[2]), "r"(a[3]), "r"(b[0]), "r"(b[1]));
}
__device__ __forceinline__ void split_bf16(float v, __nv_bfloat16& h, __nv_bfloat16& l) {
    h = __float2bfloat16(v);
    l = __float2bfloat16(v - __bfloat162float(h));
}
__device__ __forceinline__ uint32_t sw128(uint32_t b) {
    return b ^ ((b >> 3) & 0x70);
}

// ---------------- SE attention: mean over (f,n) ----------------
__global__ void k_mean(const float* __restrict__ x) {
    int bt = blockIdx.x;
    const float* p = x + (size_t)bt * FIN * NN;
    float s = 0.f;
    for (int i = threadIdx.x; i < FIN * NN; i += 256) s += p[i];
    __shared__ float sm[8];
    for (int o = 16; o; o >>= 1) s += __shfl_xor_sync(~0u, s, o);
    if ((threadIdx.x & 31) == 0) sm[threadIdx.x >> 5] = s;
    __syncthreads();
    if (threadIdx.x < 8) {
        s = sm[threadIdx.x];
        for (int o = 4; o; o >>= 1) s += __shfl_xor_sync(0xffu, s, o);
        if (threadIdx.x == 0) g_att0[bt] = s / (float)(FIN * NN);
    }
}

// ---------------- SE MLP ----------------
__global__ void k_mlp(const float* __restrict__ w1, const float* __restrict__ b1,
                      const float* __restrict__ w2, const float* __restrict__ b2) {
    int b = threadIdx.x;
    if (b >= B_) return;
    float h[3];
    #pragma unroll
    for (int j = 0; j < 3; j++) {
        float s = b1[j];
        #pragma unroll
        for (int t = 0; t < T_; t++) s += w1[j * T_ + t] * g_att0[b * T_ + t];
        h[j] = fmaxf(s, 0.f);
    }
    #pragma unroll
    for (int t = 0; t < T_; t++) {
        float s = b2[t];
        #pragma unroll
        for (int j = 0; j < 3; j++) s += w2[t * 3 + j] * h[j];
        g_att[b * T_ + t] = 1.f / (1.f + expf(-s));
    }
}

// ---------------- x_att = x * att ; bf16 hi/lo split ----------------
__global__ void k_xatt(const float* __restrict__ x) {
    size_t i = (size_t)blockIdx.x * 256 + threadIdx.x;
    int bt = (int)(i / ((size_t)FIN * NN));
    float v = x[i] * g_att[bt];
    __nv_bfloat16 h, l;
    split_bf16(v, h, l);
    g_xatth[i] = h; g_xattl[i] = l;
}

// ---------------- cheb split (mats 1,2 only) ----------------
__global__ void k_chebsplit(const float* __restrict__ cheb) {
    size_t i = (size_t)blockIdx.x * 256 + threadIdx.x;
    float v = cheb[NSQ + i];
    __nv_bfloat16 h, l;
    split_bf16(v, h, l);
    g_chebh[i] = h; g_chebl[i] = l;
}

// ---------------- HMMA bf16x3 GEMM: C[z] = A @ cheb[z+1] ----------------
// A [R x 2048] hi/lo; B = cheb (symmetric) so Bsm[n][k] = cheb[col0+n][k].
// CTA 128x128, BK=64, 8 warps (warp tile 32x64), 2-stage cp.async pipeline.
template<int LAYER>
__global__ void __launch_bounds__(256, 1) k_mma() {
    constexpr int R = (LAYER == 1) ? R1 : R2;
    const __nv_bfloat16* Ah = (LAYER == 1) ? g_xatth : g_xg1h;
    const __nv_bfloat16* Al = (LAYER == 1) ? g_xattl : g_xg1l;
    float* C = (LAYER == 1) ? g_P1 : g_P2;

    extern __shared__ char dynsm[];
    const int tid = threadIdx.x;
    const int z = blockIdx.z;
    const int row0 = blockIdx.y * BM;
    const int col0 = blockIdx.x * BN;
    const __nv_bfloat16* Bh = g_chebh + (size_t)z * NSQ;
    const __nv_bfloat16* Bl = g_chebl + (size_t)z * NSQ;

    uint32_t base = smem_u32(dynsm);
    // stage layout: [Ah 16K][Al 16K][Bh 16K][Bl 16K]
    uint32_t sAh[2], sAl[2], sBh[2], sBl[2];
    #pragma unroll
    for (int s = 0; s < 2; s++) {
        sAh[s] = base + s * STAGE_BYTES;
        sAl[s] = sAh[s] + 16384;
        sBh[s] = sAh[s] + 32768;
        sBl[s] = sAh[s] + 49152;
    }

    // loader lane mapping: 1024 chunks of 16B per 16KB tile; 256 threads x 4
    auto load_stage = [&](int it, int s) {
        const size_t kb = (size_t)it * BK;
        #pragma unroll
        for (int m = 0; m < 4; m++) {
            int cid = tid + 256 * m;
            int r = cid >> 3, c = cid & 7;
            uint32_t sw = sw128((uint32_t)(r * 128 + c * 16));
            const __nv_bfloat16* pah = Ah + (size_t)(row0 + r) * NN + kb + c * 8;
            const __nv_bfloat16* pal = Al + (size_t)(row0 + r) * NN + kb + c * 8;
            const __nv_bfloat16* pbh = Bh + (size_t)(col0 + r) * NN + kb + c * 8;
            const __nv_bfloat16* pbl = Bl + (size_t)(col0 + r) * NN + kb + c * 8;
            cp16(sAh[s] + sw, pah);
            cp16(sAl[s] + sw, pal);
            cp16(sBh[s] + sw, pbh);
            cp16(sBl[s] + sw, pbl);
        }
        asm volatile("cp.async.commit_group;" ::: "memory");
    };

    const int w = tid >> 5, lane = tid & 31;
    const int mwarp = (w & 3) * 32;      // 4 warps along M
    const int nwarp = (w >> 2) * 64;     // 2 warps along N
    const int li = lane >> 3;            // which 8x8 matrix (0..3)
    const int lr = lane & 7;             // row within matrix

    // ldmatrix per-lane bases (bytes within tile, pre-swizzle)
    // A frag: m-offset (li&1)*8, k-offset (li>>1)*16B
    const uint32_t aRow = (uint32_t)(mwarp + (li & 1) * 8 + lr);
    const uint32_t aK   = (uint32_t)((li >> 1) * 16);
    // B frag-pair: n-offset (li>>1)*8, k-offset (li&1)*16B
    const uint32_t bRow0 = (uint32_t)(nwarp + (li >> 1) * 8 + lr);
    const uint32_t bK    = (uint32_t)((li & 1) * 16);

    float acc[2][8][4];
    #pragma unroll
    for (int i = 0; i < 2; i++)
        #pragma unroll
        for (int j = 0; j < 8; j++)
            #pragma unroll
            for (int q = 0; q < 4; q++) acc[i][j][q] = 0.f;

    load_stage(0, 0);
    load_stage(1, 1);

    for (int it = 0; it < NIT; it++) {
        int s = it & 1;
        if (it < NIT - 1) asm volatile("cp.async.wait_group 1;" ::: "memory");
        else             asm volatile("cp.async.wait_group 0;" ::: "memory");
        __syncthreads();

        #pragma unroll
        for (int kk = 0; kk < 4; kk++) {
            uint32_t ah[2][4], al[2][4], bh[4][4], bl[4][4];
            #pragma unroll
            for (int mf = 0; mf < 2; mf++) {
                uint32_t byte = (aRow + mf * 16) * 128 + kk * 32 + aK;
                ldm4(ah[mf], sAh[s] + sw128(byte));
                ldm4(al[mf], sAl[s] + sw128(byte));
            }
            #pragma unroll
            for (int nf = 0; nf < 4; nf++) {
                uint32_t byte = (bRow0 + nf * 16) * 128 + kk * 32 + bK;
                ldm4(bh[nf], sBh[s] + sw128(byte));
                ldm4(bl[nf], sBl[s] + sw128(byte));
            }
            #pragma unroll
            for (int mf = 0; mf < 2; mf++) {
                #pragma unroll
                for (int j = 0; j < 8; j++) {
                    const uint32_t* bhp = &bh[j >> 1][(j & 1) * 2];
                    const uint32_t* blp = &bl[j >> 1][(j & 1) * 2];
                    mma16816(acc[mf][j], ah[mf], bhp);
                    mma16816(acc[mf][j], ah[mf], blp);
                    mma16816(acc[mf][j], al[mf], bhp);
                }
            }
        }
        __syncthreads();
        if (it + 2 < NIT) load_stage(it + 2, s);
    }

    // epilogue: write C (f32)
    const int g = lane >> 2, tq = lane & 3;
    float* Cp = C + ((size_t)z * R + row0) * NN + col0;
    #pragma unroll
    for (int mf = 0; mf < 2; mf++) {
        #pragma unroll
        for (int j = 0; j < 8; j++) {
            int r = mwarp + mf * 16 + g;
            int cc = nwarp + j * 8 + tq * 2;
            *(float2*)(Cp + (size_t)r * NN + cc) =
                make_float2(acc[mf][j][0], acc[mf][j][1]);
            *(float2*)(Cp + (size_t)(r + 8) * NN + cc) =
                make_float2(acc[mf][j][2], acc[mf][j][3]);
        }
    }
}

// ---------------- combine layer1: theta-mix + relu -> bf16 hi/lo ----------
__global__ __launch_bounds__(256)
void k_combine1(const float* __restrict__ theta1) {
    __shared__ float th[3 * FIN * FOUT];
    for (int i = threadIdx.x; i < 3 * FIN * FOUT; i += 256) th[i] = theta1[i];
    __syncthreads();
    int bt = blockIdx.y;
    int n = blockIdx.x * 256 + threadIdx.x;
    float acc[FOUT] = {};
    // k=0: cheb[0] == I -> x_att (reconstructed from hi+lo)
    const __nv_bfloat16* xh = g_xatth + ((size_t)bt * FIN) * NN + n;
    const __nv_bfloat16* xl = g_xattl + ((size_t)bt * FIN) * NN + n;
    #pragma unroll
    for (int f = 0; f < FIN; f++) {
        float v = __bfloat162float(xh[(size_t)f * NN]) + __bfloat162float(xl[(size_t)f * NN]);
        const float* tp = th + f * FOUT;
        #pragma unroll
        for (int o = 0; o < FOUT; o++) acc[o] += tp[o] * v;
    }
    #pragma unroll
    for (int k2 = 0; k2 < 2; k2++) {
        const float* p = g_P1 + ((size_t)k2 * R1 + bt * FIN) * NN + n;
        const float* tk = th + (k2 + 1) * FIN * FOUT;
        #pragma unroll
        for (int f = 0; f < FIN; f++) {
            float v = p[(size_t)f * NN];
            #pragma unroll
            for (int o = 0; o < FOUT; o++) acc[o] += tk[f * FOUT + o] * v;
        }
    }
    size_t ob = ((size_t)bt * FOUT) * NN + n;
    #pragma unroll
    for (int o = 0; o < FOUT; o++) {
        float v = fmaxf(acc[o], 0.f);
        __nv_bfloat16 h, l;
        split_bf16(v, h, l);
        g_xg1h[ob + (size_t)o * NN] = h;
        g_xg1l[ob + (size_t)o * NN] = l;
    }
}

// ---------------- combine layer2 ----------------
__global__ __launch_bounds__(256)
void k_combine2(const float* __restrict__ theta2) {
    __shared__ float th[3 * FOUT * FOUT];
    for (int i = threadIdx.x; i < 3 * FOUT * FOUT; i += 256) th[i] = theta2[i];
    __syncthreads();
    int bt = blockIdx.y;
    int n = blockIdx.x * 256 + threadIdx.x;
    float acc[FOUT] = {};
    const __nv_bfloat16* xh = g_xg1h + ((size_t)bt * FOUT) * NN + n;
    const __nv_bfloat16* xl = g_xg1l + ((size_t)bt * FOUT) * NN + n;
    #pragma unroll
    for (int f = 0; f < FOUT; f++) {
        float v = __bfloat162float(xh[(size_t)f * NN]) + __bfloat162float(xl[(size_t)f * NN]);
        const float* tp = th + f * FOUT;
        #pragma unroll
        for (int o = 0; o < FOUT; o++) acc[o] += tp[o] * v;
    }
    #pragma unroll
    for (int k2 = 0; k2 < 2; k2++) {
        const float* p = g_P2 + ((size_t)k2 * R2 + bt * FOUT) * NN + n;
        const float* tk = th + (k2 + 1) * FOUT * FOUT;
        #pragma unroll
        for (int f = 0; f < FOUT; f++) {
            float v = p[(size_t)f * NN];
            #pragma unroll
            for (int o = 0; o < FOUT; o++) acc[o] += tk[f * FOUT + o] * v;
        }
    }
    float* out = g_xg2 + ((size_t)bt * FOUT) * NN + n;
    #pragma unroll
    for (int o = 0; o < FOUT; o++) out[(size_t)o * NN] = fmaxf(acc[o], 0.f);
}

// ---------------- temporal conv 1 ----------------
__global__ __launch_bounds__(256)
void k_tconv1(const float* __restrict__ w, const float* __restrict__ bias) {
    __shared__ float ws[FOUT * FOUT * 2];
    for (int i = threadIdx.x; i < FOUT * FOUT * 2; i += 256) ws[i] = w[i];
    __syncthreads();
    int bt = blockIdx.y;
    int b = bt / T_, t = bt % T_;
    int ta = (t == 0) ? 10 : (t - 1);
    int tb = (t == 0) ? 11 : t;
    int n = blockIdx.x * 256 + threadIdx.x;
    const float* pa = g_xg2 + ((size_t)(b * T_ + ta) * FOUT) * NN + n;
    const float* pb = g_xg2 + ((size_t)(b * T_ + tb) * FOUT) * NN + n;
    float acc[FOUT];
    #pragma unroll
    for (int o = 0; o < FOUT; o++) acc[o] = bias[o];
    #pragma unroll
    for (int gg = 0; gg < FOUT; gg++) {
        float v0 = pa[(size_t)gg * NN], v1 = pb[(size_t)gg * NN];
        #pragma unroll
        for (int o = 0; o < FOUT; o++)
            acc[o] += ws[(o * FOUT + gg) * 2] * v0 + ws[(o * FOUT + gg) * 2 + 1] * v1;
    }
    float* out = g_xt1 + ((size_t)bt * FOUT) * NN + n;
    #pragma unroll
    for (int o = 0; o < FOUT; o++) out[(size_t)o * NN] = fmaxf(acc[o], 0.f);
}

// ---------------- temporal conv 2 + residual + partial LN stats ------------
__global__ __launch_bounds__(256)
void k_tconv2(const float* __restrict__ x,
              const float* __restrict__ w2, const float* __restrict__ b2,
              const float* __restrict__ rw, const float* __restrict__ rb) {
    __shared__ float ws[FOUT * FOUT * 2];
    __shared__ float rs[FOUT * FIN];
    __shared__ float red[2][8][FOUT];
    for (int i = threadIdx.x; i < FOUT * FOUT * 2; i += 256) ws[i] = w2[i];
    for (int i = threadIdx.x; i < FOUT * FIN; i += 256) rs[i] = rw[i];
    __syncthreads();
    int bt = blockIdx.y;
    int b = bt / T_, t = bt % T_;
    int ta = (t == 0) ? 10 : (t - 1);
    int tb = (t == 0) ? 11 : t;
    int n = blockIdx.x * 256 + threadIdx.x;
    const float* pa = g_xt1 + ((size_t)(b * T_ + ta) * FOUT) * NN + n;
    const float* pb = g_xt1 + ((size_t)(b * T_ + tb) * FOUT) * NN + n;
    float acc[FOUT];
    #pragma unroll
    for (int o = 0; o < FOUT; o++) acc[o] = b2[o];
    #pragma unroll
    for (int gg = 0; gg < FOUT; gg++) {
        float v0 = pa[(size_t)gg * NN], v1 = pb[(size_t)gg * NN];
        #pragma unroll
        for (int o = 0; o < FOUT; o++)
            acc[o] += ws[(o * FOUT + gg) * 2] * v0 + ws[(o * FOUT + gg) * 2 + 1] * v1;
    }
    #pragma unroll
    for (int o = 0; o < FOUT; o++) acc[o] = fmaxf(acc[o], 0.f) + rb[o];
    const float* xr = x + ((size_t)bt * FIN) * NN + n;
    #pragma unroll
    for (int f = 0; f < FIN; f++) {
        float v = xr[(size_t)f * NN];
        #pragma unroll
        for (int o = 0; o < FOUT; o++) acc[o] += rs[o * FIN + f] * v;
    }
    float* out = g_y + ((size_t)bt * FOUT) * NN + n;
    int warp = threadIdx.x >> 5, lane = threadIdx.x & 31;
    #pragma unroll
    for (int o = 0; o < FOUT; o++) {
        float v = acc[o];
        out[(size_t)o * NN] = v;
        float s = v, s2 = v * v;
        #pragma unroll
        for (int d = 16; d; d >>= 1) {
            s  += __shfl_xor_sync(~0u, s, d);
            s2 += __shfl_xor_sync(~0u, s2, d);
        }
        if (lane == 0) { red[0][warp][o] = s; red[1][warp][o] = s2; }
    }
    __syncthreads();
    if (threadIdx.x < FOUT) {
        int o = threadIdx.x;
        float s = 0.f, s2 = 0.f;
        #pragma unroll
        for (int wdx = 0; wdx < 8; wdx++) { s += red[0][wdx][o]; s2 += red[1][wdx][o]; }
        size_t base = (((size_t)bt * FOUT + o) * NCHUNK + blockIdx.x) * 2;
        g_part[base] = s;
        g_part[base + 1] = s2;
    }
}

// ---------------- layernorm + affine + relu ----------------
__global__ __launch_bounds__(256)
void k_ln(const float* __restrict__ lng, const float* __restrict__ lnb,
          float* __restrict__ out) {
    int bto = blockIdx.x;
    int n = blockIdx.y * 256 + threadIdx.x;
    float s = 0.f, s2 = 0.f;
    #pragma unroll
    for (int c = 0; c < NCHUNK; c++) {
        size_t base = (((size_t)bto) * NCHUNK + c) * 2;
        s += g_part[base];
        s2 += g_part[base + 1];
    }
    float mu = s / (float)NN;
    float var = s2 / (float)NN - mu * mu;
    float rstd = rsqrtf(var + 1e-5f);
    float v = g_y[(size_t)bto * NN + n];
    v = (v - mu) * rstd * lng[n] + lnb[n];
    out[(size_t)bto * NN + n] = fmaxf(v, 0.f);
}

// ---------------- launch ----------------
extern "C" void kernel_launch(void* const* d_in, const int* in_sizes, int n_in,
                              void* d_out, int out_size) {
    const float* x      = (const float*)d_in[0];
    const float* cheb   = (const float*)d_in[1];
    const float* theta1 = (const float*)d_in[2];
    const float* theta2 = (const float*)d_in[3];
    const float* m1w    = (const float*)d_in[4];
    const float* m1b    = (const float*)d_in[5];
    const float* m2w    = (const float*)d_in[6];
    const float* m2b    = (const float*)d_in[7];
    const float* tc1w   = (const float*)d_in[8];
    const float* tc1b   = (const float*)d_in[9];
    const float* tc2w   = (const float*)d_in[10];
    const float* tc2b   = (const float*)d_in[11];
    const float* resw   = (const float*)d_in[12];
    const float* resb   = (const float*)d_in[13];
    const float* lng    = (const float*)d_in[14];
    const float* lnb    = (const float*)d_in[15];
    float* out = (float*)d_out;

    static bool attr_done = false;
    if (!attr_done) {
        cudaFuncSetAttribute(k_mma<1>, cudaFuncAttributeMaxDynamicSharedMemorySize, DYN_SMEM);
        cudaFuncSetAttribute(k_mma<2>, cudaFuncAttributeMaxDynamicSharedMemorySize, DYN_SMEM);
        attr_done = true;
    }

    // SE attention + splits
    k_mean<<<BT, 256>>>(x);
    k_mlp<<<1, 32>>>(m1w, m1b, m2w, m2b);
    k_xatt<<<(int)(((size_t)R1 * NN) / 256), 256>>>(x);
    k_chebsplit<<<(int)((2 * NSQ) / 256), 256>>>(cheb);

    // gconv layer 1
    dim3 g1(NN / BN, R1 / BM, 2);
    k_mma<1><<<g1, 256, DYN_SMEM>>>();
    k_combine1<<<dim3(NCHUNK, BT), 256>>>(theta1);

    // gconv layer 2
    dim3 g2(NN / BN, R2 / BM, 2);
    k_mma<2><<<g2, 256, DYN_SMEM>>>();
    k_combine2<<<dim3(NCHUNK, BT), 256>>>(theta2);

    // temporal convs + residual + layernorm
    k_tconv1<<<dim3(NCHUNK, BT), 256>>>(tc1w, tc1b);
    k_tconv2<<<dim3(NCHUNK, BT), 256>>>(x, tc2w, tc2b, resw, resb);
    k_ln<<<dim3(BT * FOUT, NCHUNK), 256>>>(lng, lnb, out);
}